// round 9
// baseline (speedup 1.0000x reference)
#include <cuda_runtime.h>
#include <cuda_fp16.h>
#include <cstdint>
#include <math.h>

// Problem constants
#define N_GLOB 256
#define M_GLOB 1024
#define D_GLOB 512
#define H_GLOB 512

// Tiling
#define E_SUB    32
#define S_SUB    8
#define P_TILE   256          // pairs per CTA = 32e x 8s
#define H_TILE   128          // H per pass (4 passes)
#define K_SLAB   32           // K per phase (= 2 x k16)
#define N_PHASES 64           // 4 passes * 16 k-slabs
#define N_STAGES 4

#define THREADS  576          // 512 consumers (16 warps) + 64 producers (2 warps)
#define NCONS    512
#define NCONS_WARPS 16

// SMEM layout (byte offsets)
#define MBAR_OFF 0            // full[4] @ 0,8,16,24 ; empty[4] @ 32,40,48,56
#define B1_OFF   128          // 512 f32
#define W2_OFF   2176         // 512 f32
#define PART_OFF 4224         // 256 f32
#define ES_OFF   5248         // [32][520] half  (33280 B)
#define SS_OFF   38528        // [8][520] half   (8320 B)
#define STAGE_OFF 46848       // 4 stages x 26624 B
#define STAGE_BYTES 26624     // A: 32 pids x 512 B = 16384 ; B: 128 rows x 80 B = 10240
#define A_IN_STAGE  0
#define B_IN_STAGE  16384
#define SMEM_BYTES 153344

#define B_ROWB   80           // bytes per B row (32 data halfs + 8 pad), 16B-aligned

__device__ static __half g_W1T[H_GLOB * D_GLOB];   // W1 transposed [h][k], fp16

__device__ __forceinline__ uint32_t smem_u32(const void* p) {
    uint32_t a;
    asm("{ .reg .u64 t; cvta.to.shared.u64 t, %1; cvt.u32.u64 %0, t; }" : "=r"(a) : "l"(p));
    return a;
}
__device__ __forceinline__ void cpa16(uint32_t s, const void* g) {
    asm volatile("cp.async.cg.shared.global [%0], [%1], 16;" :: "r"(s), "l"(g));
}
#define MBARRIER_INIT(addr, cnt) \
    asm volatile("mbarrier.init.shared.b64 [%0], %1;" :: "r"((uint32_t)(addr)), "r"((uint32_t)(cnt)) : "memory")
#define MBARRIER_ARRIVE(addr) \
    asm volatile("mbarrier.arrive.shared.b64 _, [%0];" :: "r"((uint32_t)(addr)) : "memory")
#define CPASYNC_MBAR_ARRIVE(addr) \
    asm volatile("cp.async.mbarrier.arrive.noinc.shared.b64 [%0];" :: "r"((uint32_t)(addr)) : "memory")
#define MBARRIER_WAIT_PARITY(addr, parity) do { \
    uint32_t _m = (uint32_t)(addr); uint32_t _p = (uint32_t)(parity); uint32_t _d; \
    asm volatile("{\n\t.reg .pred p;\n\t" \
        "mbarrier.try_wait.parity.acquire.cta.shared::cta.b64 p, [%1], %2;\n\t" \
        "selp.b32 %0, 1, 0, p;\n\t}" : "=r"(_d) : "r"(_m), "r"(_p) : "memory"); \
    if (!_d) { \
        asm volatile("{\n\t.reg .pred P1;\n\t" \
            "WL_%=:\n\t" \
            "mbarrier.try_wait.parity.acquire.cta.shared::cta.b64 P1, [%0], %1, 0x989680;\n\t" \
            "@P1 bra.uni WD_%=;\n\t" \
            "bra.uni WL_%=;\n\t" \
            "WD_%=:\n\t}" :: "r"(_m), "r"(_p) : "memory"); \
    } } while (0)

__device__ __forceinline__ uint32_t h2_u32(__half2 h) {
    uint32_t u;
    __builtin_memcpy(&u, &h, 4);
    return u;
}

// ---- pre-kernel: W1 [D][H] f32  ->  g_W1T [H][D] fp16 ----
__global__ void convert_w1_kernel(const float* __restrict__ W1) {
    __shared__ float tile[32][33];
    const int kx = blockIdx.x * 32;
    const int hx = blockIdx.y * 32;
    const int x = threadIdx.x, y = threadIdx.y;   // 32 x 8
    #pragma unroll
    for (int i = 0; i < 32; i += 8)
        tile[y + i][x] = W1[(size_t)(kx + y + i) * H_GLOB + hx + x];
    __syncthreads();
    #pragma unroll
    for (int i = 0; i < 32; i += 8)
        g_W1T[(size_t)(hx + y + i) * D_GLOB + kx + x] = __float2half(tile[x][y + i]);
}

__global__ void __launch_bounds__(THREADS, 1)
support_ws_kernel(const float* __restrict__ E,   // [N, D]
                  const float* __restrict__ S,   // [M, D]
                  const float* __restrict__ B1,  // [H]
                  const float* __restrict__ W2,  // [H]
                  const float* __restrict__ B2,  // [1]
                  float* __restrict__ out)       // [N, M]
{
    extern __shared__ char smem[];
    __half* smE  = (__half*)(smem + ES_OFF);
    __half* smS  = (__half*)(smem + SS_OFF);
    float*  smB1 = (float*)(smem + B1_OFF);
    float*  smW2 = (float*)(smem + W2_OFF);
    float*  smP  = (float*)(smem + PART_OFF);
    const uint32_t smb = smem_u32(smem);

    const int tid  = threadIdx.x;
    const int wid  = tid >> 5;
    const int lane = tid & 31;

    const int n0 = blockIdx.y * E_SUB;
    const int m0 = blockIdx.x * S_SUB;

    // ---- prologue: mbarriers, E/S fp16 staging, b1/w2, partials ----
    if (tid == 0) {
        #pragma unroll
        for (int s = 0; s < N_STAGES; ++s) {
            MBARRIER_INIT(smb + MBAR_OFF + s * 8, 128);              // full: 64 STS + 64 cp.async
            MBARRIER_INIT(smb + MBAR_OFF + 32 + s * 8, NCONS_WARPS); // empty: 16 elected arrives
        }
    }
    for (int i = tid; i < 8192; i += THREADS) {       // E -> fp16 [32][520]
        const int row = i >> 8, c = i & 255;
        const float2 v = *(const float2*)(E + (size_t)(n0 + row) * D_GLOB + c * 2);
        *(__half2*)(smE + row * 520 + c * 2) = __floats2half2_rn(v.x, v.y);
    }
    for (int i = tid; i < 2048; i += THREADS) {       // S -> fp16 [8][520]
        const int row = i >> 8, c = i & 255;
        const float2 v = *(const float2*)(S + (size_t)(m0 + row) * D_GLOB + c * 2);
        *(__half2*)(smS + row * 520 + c * 2) = __floats2half2_rn(v.x, v.y);
    }
    for (int i = tid; i < 512; i += THREADS) { smB1[i] = B1[i]; smW2[i] = W2[i]; }
    if (tid < 256) smP[tid] = 0.f;
    __syncthreads();

    if (wid >= 16) {
        // ================= PRODUCER (2 warps, 64 threads) =================
        const int pw = wid - 16;          // 0..1
        const int pt = tid - NCONS;       // 0..63
        const int c  = lane & 3;
        const int r  = lane >> 2;

        for (int p = 0; p < N_PHASES; ++p) {
            const int st   = p & 3;
            const int ph   = (p >> 2) & 1;
            const int slab = p & 15;
            const int pass = p >> 4;
            const uint32_t stg = smb + STAGE_OFF + st * STAGE_BYTES;

            MBARRIER_WAIT_PARITY(smb + MBAR_OFF + 32 + st * 8, ph ^ 1);  // wait empty

            // --- build A frags (fp16) into stage st: 32 pids = (mt_g<<1)|kt ---
            char* stA = smem + STAGE_OFF + st * STAGE_BYTES + A_IN_STAGE;
            #pragma unroll
            for (int j = 0; j < 16; ++j) {
                const int pid  = j * 2 + pw;       // 0..31
                const int mt_g = pid >> 1;
                const int kt   = pid & 1;
                const int row0 = mt_g * 2;
                const int kb   = slab * 32 + kt * 16 + c * 2;
                const __half2 e0  = *(const __half2*)(smE + row0 * 520 + kb);
                const __half2 e0b = *(const __half2*)(smE + row0 * 520 + kb + 8);
                const __half2 e1  = *(const __half2*)(smE + (row0 + 1) * 520 + kb);
                const __half2 e1b = *(const __half2*)(smE + (row0 + 1) * 520 + kb + 8);
                const __half2 s0  = *(const __half2*)(smS + r * 520 + kb);
                const __half2 s0b = *(const __half2*)(smS + r * 520 + kb + 8);
                uint4 v;
                v.x = h2_u32(__habs2(__hsub2(e0,  s0)));
                v.y = h2_u32(__habs2(__hsub2(e1,  s0)));
                v.z = h2_u32(__habs2(__hsub2(e0b, s0b)));
                v.w = h2_u32(__habs2(__hsub2(e1b, s0b)));
                *(uint4*)(stA + pid * 512 + lane * 16) = v;
            }
            MBARRIER_ARRIVE(smb + MBAR_OFF + st * 8);   // A visible (release)

            // --- B slab cp.async into stage st: [128 h][32 k] fp16, row 80 B ---
            #pragma unroll
            for (int j = 0; j < 8; ++j) {
                const int idx = pt + j * 64;            // 0..511
                const int h = idx >> 2, q = idx & 3;
                cpa16(stg + B_IN_STAGE + h * B_ROWB + q * 16,
                      g_W1T + (size_t)(pass * H_TILE + h) * D_GLOB + slab * K_SLAB + q * 8);
            }
            CPASYNC_MBAR_ARRIVE(smb + MBAR_OFF + st * 8);  // arrives when cp.asyncs land
        }
    } else {
        // ============ CONSUMER (16 warps, 64 rows x 32 cols each) ============
        const int warp_m = wid & 3;
        const int warp_n = wid >> 2;
        const int c  = lane & 3;
        // ldmatrix per-lane address pieces (R8-validated mapping)
        const int g    = lane >> 3;
        const int lrow = ((g >> 1) << 3) + (lane & 7);  // 0..15 within 16-row group
        const int lcol = (g & 1) * 8;                   // k offset 0 / 8

        float acc[4][4][4];
        float psum[8];
        #pragma unroll
        for (int i = 0; i < 8; ++i) psum[i] = 0.f;

        for (int p = 0; p < N_PHASES; ++p) {
            const int st   = p & 3;
            const int ph   = (p >> 2) & 1;
            const int slab = p & 15;
            const int pass = p >> 4;

            MBARRIER_WAIT_PARITY(smb + MBAR_OFF + st * 8, ph);   // wait full

            // ---- load ALL fragments for this phase into registers ----
            const char*    bA = smem + STAGE_OFF + st * STAGE_BYTES + A_IN_STAGE;
            const uint32_t bB = smb + STAGE_OFF + st * STAGE_BYTES + B_IN_STAGE;
            uint4 af[2][4];
            #pragma unroll
            for (int kt = 0; kt < 2; ++kt)
                #pragma unroll
                for (int mt = 0; mt < 4; ++mt)
                    af[kt][mt] = *(const uint4*)(bA + (((warp_m * 4 + mt) * 2 + kt) * 32 + lane) * 16);
            uint32_t bq[2][4][2];
            #pragma unroll
            for (int kt = 0; kt < 2; ++kt)
                #pragma unroll
                for (int j = 0; j < 2; ++j) {
                    const uint32_t addr = bB + (uint32_t)(warp_n * 32 + j * 16 + lrow) * B_ROWB
                                             + (uint32_t)(kt * 16 + lcol) * 2;
                    asm volatile(
                        "ldmatrix.sync.aligned.m8n8.x4.shared.b16 {%0, %1, %2, %3}, [%4];"
                        : "=r"(bq[kt][j * 2][0]), "=r"(bq[kt][j * 2][1]),
                          "=r"(bq[kt][j * 2 + 1][0]), "=r"(bq[kt][j * 2 + 1][1])
                        : "r"(addr));
                }

            // ---- early release: frags are in regs, stage reusable ----
            if (lane == 0) MBARRIER_ARRIVE(smb + MBAR_OFF + 32 + st * 8);

            if (slab == 0) {
                #pragma unroll
                for (int mt = 0; mt < 4; ++mt)
                    #pragma unroll
                    for (int nt = 0; nt < 4; ++nt)
                        #pragma unroll
                        for (int q = 0; q < 4; ++q) acc[mt][nt][q] = 0.f;
            }

            #pragma unroll
            for (int kt = 0; kt < 2; ++kt)
                #pragma unroll
                for (int mt = 0; mt < 4; ++mt)
                    #pragma unroll
                    for (int nt = 0; nt < 4; ++nt) {
                        asm volatile(
                            "mma.sync.aligned.m16n8k16.row.col.f32.f16.f16.f32 "
                            "{%0,%1,%2,%3}, {%4,%5,%6,%7}, {%8,%9}, {%0,%1,%2,%3};\n"
                            : "+f"(acc[mt][nt][0]), "+f"(acc[mt][nt][1]),
                              "+f"(acc[mt][nt][2]), "+f"(acc[mt][nt][3])
                            : "r"(af[kt][mt].x), "r"(af[kt][mt].y),
                              "r"(af[kt][mt].z), "r"(af[kt][mt].w),
                              "r"(bq[kt][nt][0]), "r"(bq[kt][nt][1]));
                    }

            if (slab == 15) {
                #pragma unroll
                for (int mt = 0; mt < 4; ++mt)
                    #pragma unroll
                    for (int nt = 0; nt < 4; ++nt) {
                        const int jg = pass * H_TILE + warp_n * 32 + nt * 8 + c * 2;
                        const float b1a = smB1[jg], b1b = smB1[jg + 1];
                        const float w2a = smW2[jg], w2b = smW2[jg + 1];
                        const float h0 = fmaxf(acc[mt][nt][0] + b1a, 0.f);
                        const float h1 = fmaxf(acc[mt][nt][1] + b1b, 0.f);
                        const float h2 = fmaxf(acc[mt][nt][2] + b1a, 0.f);
                        const float h3 = fmaxf(acc[mt][nt][3] + b1b, 0.f);
                        psum[mt * 2 + 0] += h0 * w2a + h1 * w2b;
                        psum[mt * 2 + 1] += h2 * w2a + h3 * w2b;
                    }
            }
        }

        // reduce across quad (k-cols of frag), then across n-warps via smem atomics
        #pragma unroll
        for (int i = 0; i < 8; ++i) {
            psum[i] += __shfl_xor_sync(0xffffffffu, psum[i], 1);
            psum[i] += __shfl_xor_sync(0xffffffffu, psum[i], 2);
        }
        if (c == 0) {
            const int r = lane >> 2;
            #pragma unroll
            for (int mt = 0; mt < 4; ++mt) {
                atomicAdd(&smP[warp_m * 64 + mt * 16 + r],     psum[mt * 2 + 0]);
                atomicAdd(&smP[warp_m * 64 + mt * 16 + r + 8], psum[mt * 2 + 1]);
            }
        }
    }

    __syncthreads();
    if (tid < P_TILE) {
        const float logit = smP[tid] + B2[0];
        const int n = n0 + (tid >> 3);
        const int m = m0 + (tid & 7);
        out[(size_t)n * M_GLOB + m] = 1.f / (1.f + expf(-logit));
    }
}

extern "C" void kernel_launch(void* const* d_in, const int* in_sizes, int n_in,
                              void* d_out, int out_size)
{
    const float* E  = (const float*)d_in[0];
    const float* S  = (const float*)d_in[1];
    const float* W1 = (const float*)d_in[2];
    const float* B1 = (const float*)d_in[3];
    const float* W2 = (const float*)d_in[4];
    const float* B2 = (const float*)d_in[5];
    float* out = (float*)d_out;

    convert_w1_kernel<<<dim3(16, 16), dim3(32, 8)>>>(W1);

    cudaFuncSetAttribute(support_ws_kernel,
                         cudaFuncAttributeMaxDynamicSharedMemorySize, SMEM_BYTES);
    dim3 grid(M_GLOB / S_SUB, N_GLOB / E_SUB);   // (128, 8) = 1024 CTAs
    support_ws_kernel<<<grid, THREADS, SMEM_BYTES>>>(E, S, B1, W2, B2, out);
}

// round 10
// speedup vs baseline: 1.9540x; 1.9540x over previous
#include <cuda_runtime.h>
#include <cuda_fp16.h>
#include <cstdint>
#include <math.h>

// Problem constants
#define N_GLOB 256
#define M_GLOB 1024
#define D_GLOB 512
#define H_GLOB 512

// Tiling
#define E_SUB    32
#define S_SUB    8
#define P_TILE   256          // pairs per CTA = 32e x 8s
#define H_TILE   128          // H per pass (4 passes)
#define K_SLAB   32           // K per phase (= 2 x k16)
#define N_PHASES 64           // 4 passes * 16 k-slabs
#define N_STAGES 4

#define THREADS  576          // 512 consumers (16 warps) + 64 producers (2 warps)
#define NCONS    512
#define NCONS_WARPS 16

// SMEM layout (byte offsets)
#define MBAR_OFF 0            // full[4] @ 0,8,16,24 ; empty[4] @ 32,40,48,56
#define B1_OFF   128          // 512 f32
#define W2_OFF   2176         // 512 f32
#define PART_OFF 4224         // 256 f32
#define ES_OFF   5248         // [32][520] half  (33280 B)
#define SS_OFF   38528        // [8][520] half   (8320 B)
#define STAGE_OFF 46848       // 4 stages x 26624 B
#define STAGE_BYTES 26624     // A: 32 pids x 512 B = 16384 ; B: 128 rows x 80 B = 10240
#define A_IN_STAGE  0
#define B_IN_STAGE  16384
#define SMEM_BYTES 153344

#define B_ROWB   80           // bytes per B row (32 data halfs + 8 pad), 16B-aligned

__device__ static __half g_W1T[H_GLOB * D_GLOB];   // W1 transposed [h][k], fp16

__device__ __forceinline__ uint32_t smem_u32(const void* p) {
    uint32_t a;
    asm("{ .reg .u64 t; cvta.to.shared.u64 t, %1; cvt.u32.u64 %0, t; }" : "=r"(a) : "l"(p));
    return a;
}
__device__ __forceinline__ void cpa16(uint32_t s, const void* g) {
    asm volatile("cp.async.cg.shared.global [%0], [%1], 16;" :: "r"(s), "l"(g));
}
#define MBARRIER_INIT(addr, cnt) \
    asm volatile("mbarrier.init.shared.b64 [%0], %1;" :: "r"((uint32_t)(addr)), "r"((uint32_t)(cnt)) : "memory")
#define MBARRIER_ARRIVE(addr) \
    asm volatile("mbarrier.arrive.shared.b64 _, [%0];" :: "r"((uint32_t)(addr)) : "memory")
#define CPASYNC_MBAR_ARRIVE(addr) \
    asm volatile("cp.async.mbarrier.arrive.noinc.shared.b64 [%0];" :: "r"((uint32_t)(addr)) : "memory")
#define MBARRIER_WAIT_PARITY(addr, parity) do { \
    uint32_t _m = (uint32_t)(addr); uint32_t _p = (uint32_t)(parity); uint32_t _d; \
    asm volatile("{\n\t.reg .pred p;\n\t" \
        "mbarrier.try_wait.parity.acquire.cta.shared::cta.b64 p, [%1], %2;\n\t" \
        "selp.b32 %0, 1, 0, p;\n\t}" : "=r"(_d) : "r"(_m), "r"(_p) : "memory"); \
    if (!_d) { \
        asm volatile("{\n\t.reg .pred P1;\n\t" \
            "WL_%=:\n\t" \
            "mbarrier.try_wait.parity.acquire.cta.shared::cta.b64 P1, [%0], %1, 0x989680;\n\t" \
            "@P1 bra.uni WD_%=;\n\t" \
            "bra.uni WL_%=;\n\t" \
            "WD_%=:\n\t}" :: "r"(_m), "r"(_p) : "memory"); \
    } } while (0)

__device__ __forceinline__ uint32_t h2_u32(__half2 h) {
    uint32_t u;
    __builtin_memcpy(&u, &h, 4);
    return u;
}

// ---- pre-kernel: W1 [D][H] f32  ->  g_W1T [H][D] fp16 ----
__global__ void convert_w1_kernel(const float* __restrict__ W1) {
    __shared__ float tile[32][33];
    const int kx = blockIdx.x * 32;
    const int hx = blockIdx.y * 32;
    const int x = threadIdx.x, y = threadIdx.y;   // 32 x 8
    #pragma unroll
    for (int i = 0; i < 32; i += 8)
        tile[y + i][x] = W1[(size_t)(kx + y + i) * H_GLOB + hx + x];
    __syncthreads();
    #pragma unroll
    for (int i = 0; i < 32; i += 8)
        g_W1T[(size_t)(hx + y + i) * D_GLOB + kx + x] = __float2half(tile[x][y + i]);
}

__global__ void __launch_bounds__(THREADS, 1)
support_ws_kernel(const float* __restrict__ E,   // [N, D]
                  const float* __restrict__ S,   // [M, D]
                  const float* __restrict__ B1,  // [H]
                  const float* __restrict__ W2,  // [H]
                  const float* __restrict__ B2,  // [1]
                  float* __restrict__ out)       // [N, M]
{
    extern __shared__ char smem[];
    __half* smE  = (__half*)(smem + ES_OFF);
    __half* smS  = (__half*)(smem + SS_OFF);
    float*  smB1 = (float*)(smem + B1_OFF);
    float*  smW2 = (float*)(smem + W2_OFF);
    float*  smP  = (float*)(smem + PART_OFF);
    const uint32_t smb = smem_u32(smem);

    const int tid  = threadIdx.x;
    const int wid  = tid >> 5;
    const int lane = tid & 31;

    const int n0 = blockIdx.y * E_SUB;
    const int m0 = blockIdx.x * S_SUB;

    // ---- prologue: mbarriers, E/S fp16 staging, b1/w2, partials ----
    if (tid == 0) {
        #pragma unroll
        for (int s = 0; s < N_STAGES; ++s) {
            MBARRIER_INIT(smb + MBAR_OFF + s * 8, 128);              // full: 64 STS + 64 cp.async
            MBARRIER_INIT(smb + MBAR_OFF + 32 + s * 8, NCONS_WARPS); // empty: 16 elected arrives
        }
    }
    for (int i = tid; i < 8192; i += THREADS) {       // E -> fp16 [32][520]
        const int row = i >> 8, c = i & 255;
        const float2 v = *(const float2*)(E + (size_t)(n0 + row) * D_GLOB + c * 2);
        *(__half2*)(smE + row * 520 + c * 2) = __floats2half2_rn(v.x, v.y);
    }
    for (int i = tid; i < 2048; i += THREADS) {       // S -> fp16 [8][520]
        const int row = i >> 8, c = i & 255;
        const float2 v = *(const float2*)(S + (size_t)(m0 + row) * D_GLOB + c * 2);
        *(__half2*)(smS + row * 520 + c * 2) = __floats2half2_rn(v.x, v.y);
    }
    for (int i = tid; i < 512; i += THREADS) { smB1[i] = B1[i]; smW2[i] = W2[i]; }
    if (tid < 256) smP[tid] = 0.f;
    __syncthreads();

    if (wid >= 16) {
        // ================= PRODUCER (2 warps, 64 threads) =================
        const int pw = wid - 16;          // 0..1
        const int pt = tid - NCONS;       // 0..63
        const int c  = lane & 3;
        const int r  = lane >> 2;

        for (int p = 0; p < N_PHASES; ++p) {
            const int st   = p & 3;
            const int ph   = (p >> 2) & 1;
            const int slab = p & 15;
            const int pass = p >> 4;
            const uint32_t stg = smb + STAGE_OFF + st * STAGE_BYTES;

            MBARRIER_WAIT_PARITY(smb + MBAR_OFF + 32 + st * 8, ph ^ 1);  // wait empty

            // --- build A frags (fp16) into stage st: 32 pids = (mt_g<<1)|kt ---
            char* stA = smem + STAGE_OFF + st * STAGE_BYTES + A_IN_STAGE;
            #pragma unroll
            for (int j = 0; j < 16; ++j) {
                const int pid  = j * 2 + pw;       // 0..31
                const int mt_g = pid >> 1;
                const int kt   = pid & 1;
                const int row0 = mt_g * 2;
                const int kb   = slab * 32 + kt * 16 + c * 2;
                const __half2 e0  = *(const __half2*)(smE + row0 * 520 + kb);
                const __half2 e0b = *(const __half2*)(smE + row0 * 520 + kb + 8);
                const __half2 e1  = *(const __half2*)(smE + (row0 + 1) * 520 + kb);
                const __half2 e1b = *(const __half2*)(smE + (row0 + 1) * 520 + kb + 8);
                const __half2 s0  = *(const __half2*)(smS + r * 520 + kb);
                const __half2 s0b = *(const __half2*)(smS + r * 520 + kb + 8);
                uint4 v;
                v.x = h2_u32(__habs2(__hsub2(e0,  s0)));
                v.y = h2_u32(__habs2(__hsub2(e1,  s0)));
                v.z = h2_u32(__habs2(__hsub2(e0b, s0b)));
                v.w = h2_u32(__habs2(__hsub2(e1b, s0b)));
                *(uint4*)(stA + pid * 512 + lane * 16) = v;
            }
            MBARRIER_ARRIVE(smb + MBAR_OFF + st * 8);   // A visible (release)

            // --- B slab cp.async into stage st: [128 h][32 k] fp16, row 80 B ---
            #pragma unroll
            for (int j = 0; j < 8; ++j) {
                const int idx = pt + j * 64;            // 0..511
                const int h = idx >> 2, q = idx & 3;
                cpa16(stg + B_IN_STAGE + h * B_ROWB + q * 16,
                      g_W1T + (size_t)(pass * H_TILE + h) * D_GLOB + slab * K_SLAB + q * 8);
            }
            CPASYNC_MBAR_ARRIVE(smb + MBAR_OFF + st * 8);  // arrives when cp.asyncs land
        }
    } else {
        // ============ CONSUMER (16 warps, 64 rows x 32 cols each) ============
        const int warp_m = wid & 3;
        const int warp_n = wid >> 2;
        const int c  = lane & 3;
        // ldmatrix per-lane address pieces (R8-validated mapping)
        const int g    = lane >> 3;
        const int lrow = ((g >> 1) << 3) + (lane & 7);  // 0..15 within 16-row group
        const int lcol = (g & 1) * 8;                   // k offset 0 / 8

        float acc[4][4][4];
        float psum[8];
        #pragma unroll
        for (int i = 0; i < 8; ++i) psum[i] = 0.f;

        for (int p = 0; p < N_PHASES; ++p) {
            const int st   = p & 3;
            const int ph   = (p >> 2) & 1;
            const int slab = p & 15;
            const int pass = p >> 4;

            MBARRIER_WAIT_PARITY(smb + MBAR_OFF + st * 8, ph);   // wait full

            if (slab == 0) {
                #pragma unroll
                for (int mt = 0; mt < 4; ++mt)
                    #pragma unroll
                    for (int nt = 0; nt < 4; ++nt)
                        #pragma unroll
                        for (int q = 0; q < 4; ++q) acc[mt][nt][q] = 0.f;
            }

            const char*    bA = smem + STAGE_OFF + st * STAGE_BYTES + A_IN_STAGE;
            const uint32_t bB = smb + STAGE_OFF + st * STAGE_BYTES + B_IN_STAGE;
            #pragma unroll
            for (int kt = 0; kt < 2; ++kt) {
                uint4 af[4];
                #pragma unroll
                for (int mt = 0; mt < 4; ++mt)
                    af[mt] = *(const uint4*)(bA + (((warp_m * 4 + mt) * 2 + kt) * 32 + lane) * 16);
                uint32_t bq[4][2];
                #pragma unroll
                for (int j = 0; j < 2; ++j) {
                    const uint32_t addr = bB + (uint32_t)(warp_n * 32 + j * 16 + lrow) * B_ROWB
                                             + (uint32_t)(kt * 16 + lcol) * 2;
                    asm volatile(
                        "ldmatrix.sync.aligned.m8n8.x4.shared.b16 {%0, %1, %2, %3}, [%4];"
                        : "=r"(bq[j * 2][0]), "=r"(bq[j * 2][1]),
                          "=r"(bq[j * 2 + 1][0]), "=r"(bq[j * 2 + 1][1])
                        : "r"(addr));
                }
                #pragma unroll
                for (int mt = 0; mt < 4; ++mt)
                    #pragma unroll
                    for (int nt = 0; nt < 4; ++nt) {
                        asm volatile(
                            "mma.sync.aligned.m16n8k16.row.col.f32.f16.f16.f32 "
                            "{%0,%1,%2,%3}, {%4,%5,%6,%7}, {%8,%9}, {%0,%1,%2,%3};\n"
                            : "+f"(acc[mt][nt][0]), "+f"(acc[mt][nt][1]),
                              "+f"(acc[mt][nt][2]), "+f"(acc[mt][nt][3])
                            : "r"(af[mt].x), "r"(af[mt].y), "r"(af[mt].z), "r"(af[mt].w),
                              "r"(bq[nt][0]), "r"(bq[nt][1]));
                    }
            }
            // elected per-warp release (count 16): kills single-address ATOMS serialization
            if (lane == 0) MBARRIER_ARRIVE(smb + MBAR_OFF + 32 + st * 8);

            if (slab == 15) {
                #pragma unroll
                for (int mt = 0; mt < 4; ++mt)
                    #pragma unroll
                    for (int nt = 0; nt < 4; ++nt) {
                        const int jg = pass * H_TILE + warp_n * 32 + nt * 8 + c * 2;
                        const float b1a = smB1[jg], b1b = smB1[jg + 1];
                        const float w2a = smW2[jg], w2b = smW2[jg + 1];
                        const float h0 = fmaxf(acc[mt][nt][0] + b1a, 0.f);
                        const float h1 = fmaxf(acc[mt][nt][1] + b1b, 0.f);
                        const float h2 = fmaxf(acc[mt][nt][2] + b1a, 0.f);
                        const float h3 = fmaxf(acc[mt][nt][3] + b1b, 0.f);
                        psum[mt * 2 + 0] += h0 * w2a + h1 * w2b;
                        psum[mt * 2 + 1] += h2 * w2a + h3 * w2b;
                    }
            }
        }

        // reduce across quad (k-cols of frag), then across n-warps via smem atomics
        #pragma unroll
        for (int i = 0; i < 8; ++i) {
            psum[i] += __shfl_xor_sync(0xffffffffu, psum[i], 1);
            psum[i] += __shfl_xor_sync(0xffffffffu, psum[i], 2);
        }
        if (c == 0) {
            const int r = lane >> 2;
            #pragma unroll
            for (int mt = 0; mt < 4; ++mt) {
                atomicAdd(&smP[warp_m * 64 + mt * 16 + r],     psum[mt * 2 + 0]);
                atomicAdd(&smP[warp_m * 64 + mt * 16 + r + 8], psum[mt * 2 + 1]);
            }
        }
    }

    __syncthreads();
    if (tid < P_TILE) {
        const float logit = smP[tid] + B2[0];
        const int n = n0 + (tid >> 3);
        const int m = m0 + (tid & 7);
        out[(size_t)n * M_GLOB + m] = 1.f / (1.f + expf(-logit));
    }
}

extern "C" void kernel_launch(void* const* d_in, const int* in_sizes, int n_in,
                              void* d_out, int out_size)
{
    const float* E  = (const float*)d_in[0];
    const float* S  = (const float*)d_in[1];
    const float* W1 = (const float*)d_in[2];
    const float* B1 = (const float*)d_in[3];
    const float* W2 = (const float*)d_in[4];
    const float* B2 = (const float*)d_in[5];
    float* out = (float*)d_out;

    convert_w1_kernel<<<dim3(16, 16), dim3(32, 8)>>>(W1);

    cudaFuncSetAttribute(support_ws_kernel,
                         cudaFuncAttributeMaxDynamicSharedMemorySize, SMEM_BYTES);
    dim3 grid(M_GLOB / S_SUB, N_GLOB / E_SUB);   // (128, 8) = 1024 CTAs
    support_ws_kernel<<<grid, THREADS, SMEM_BYTES>>>(E, S, B1, W2, B2, out);
}

// round 11
// speedup vs baseline: 2.0247x; 1.0362x over previous
#include <cuda_runtime.h>
#include <cuda_fp16.h>
#include <cstdint>
#include <math.h>

// Problem constants
#define N_GLOB 256
#define M_GLOB 1024
#define D_GLOB 512
#define H_GLOB 512

// Tiling: 2 CTAs/SM, each 128 pairs = 16e x 8s
#define E_SUB    16
#define S_SUB    8
#define P_TILE   128
#define H_TILE   128          // H per pass (4 passes)
#define K_SLAB   32           // K per phase (= 2 x k16)
#define N_PHASES 64           // 4 passes * 16 k-slabs
#define N_STAGES 4

#define THREADS  288          // 256 consumers (8 warps) + 32 producers (1 warp)
#define NCONS    256

// SMEM layout (byte offsets)
#define MBAR_OFF 0            // full[4] @ 0,8,16,24 ; empty[4] @ 32,40,48,56
#define B1_OFF   128          // 512 f32
#define W2_OFF   2176         // 512 f32
#define PART_OFF 4224         // 128 f32
#define ES_OFF   4736         // [16][520] half  (16640 B)
#define SS_OFF   21376        // [8][520]  half  (8320 B)
#define STAGE_OFF 29696       // 4 stages x 18432 B
#define STAGE_BYTES 18432     // A: 16 pids x 512 B = 8192 ; B: 128 rows x 80 B = 10240
#define A_IN_STAGE  0
#define B_IN_STAGE  8192
#define SMEM_BYTES 103424

#define B_PADH   40           // halfs per B row (32 data + 8 pad)

__device__ static __half g_W1T[H_GLOB * D_GLOB];   // W1 transposed [h][k], fp16

__device__ __forceinline__ uint32_t smem_u32(const void* p) {
    uint32_t a;
    asm("{ .reg .u64 t; cvta.to.shared.u64 t, %1; cvt.u32.u64 %0, t; }" : "=r"(a) : "l"(p));
    return a;
}
__device__ __forceinline__ void cpa16(uint32_t s, const void* g) {
    asm volatile("cp.async.cg.shared.global [%0], [%1], 16;" :: "r"(s), "l"(g));
}
#define MBARRIER_INIT(addr, cnt) \
    asm volatile("mbarrier.init.shared.b64 [%0], %1;" :: "r"((uint32_t)(addr)), "r"((uint32_t)(cnt)) : "memory")
#define MBARRIER_ARRIVE(addr) \
    asm volatile("mbarrier.arrive.shared.b64 _, [%0];" :: "r"((uint32_t)(addr)) : "memory")
#define CPASYNC_MBAR_ARRIVE(addr) \
    asm volatile("cp.async.mbarrier.arrive.noinc.shared.b64 [%0];" :: "r"((uint32_t)(addr)) : "memory")
#define MBARRIER_WAIT_PARITY(addr, parity) do { \
    uint32_t _m = (uint32_t)(addr); uint32_t _p = (uint32_t)(parity); uint32_t _d; \
    asm volatile("{\n\t.reg .pred p;\n\t" \
        "mbarrier.try_wait.parity.acquire.cta.shared::cta.b64 p, [%1], %2;\n\t" \
        "selp.b32 %0, 1, 0, p;\n\t}" : "=r"(_d) : "r"(_m), "r"(_p) : "memory"); \
    if (!_d) { \
        asm volatile("{\n\t.reg .pred P1;\n\t" \
            "WL_%=:\n\t" \
            "mbarrier.try_wait.parity.acquire.cta.shared::cta.b64 P1, [%0], %1, 0x989680;\n\t" \
            "@P1 bra.uni WD_%=;\n\t" \
            "bra.uni WL_%=;\n\t" \
            "WD_%=:\n\t}" :: "r"(_m), "r"(_p) : "memory"); \
    } } while (0)

__device__ __forceinline__ uint32_t h2_u32(__half2 h) {
    uint32_t u;
    __builtin_memcpy(&u, &h, 4);
    return u;
}

// ---- pre-kernel: W1 [D][H] f32  ->  g_W1T [H][D] fp16 ----
__global__ void convert_w1_kernel(const float* __restrict__ W1) {
    __shared__ float tile[32][33];
    const int kx = blockIdx.x * 32;
    const int hx = blockIdx.y * 32;
    const int x = threadIdx.x, y = threadIdx.y;   // 32 x 8
    #pragma unroll
    for (int i = 0; i < 32; i += 8)
        tile[y + i][x] = W1[(size_t)(kx + y + i) * H_GLOB + hx + x];
    __syncthreads();
    #pragma unroll
    for (int i = 0; i < 32; i += 8)
        g_W1T[(size_t)(hx + y + i) * D_GLOB + kx + x] = __float2half(tile[x][y + i]);
}

__global__ void __launch_bounds__(THREADS, 2)
support_ws_kernel(const float* __restrict__ E,   // [N, D]
                  const float* __restrict__ S,   // [M, D]
                  const float* __restrict__ B1,  // [H]
                  const float* __restrict__ W2,  // [H]
                  const float* __restrict__ B2,  // [1]
                  float* __restrict__ out)       // [N, M]
{
    extern __shared__ char smem[];
    __half* smE  = (__half*)(smem + ES_OFF);
    __half* smS  = (__half*)(smem + SS_OFF);
    float*  smB1 = (float*)(smem + B1_OFF);
    float*  smW2 = (float*)(smem + W2_OFF);
    float*  smP  = (float*)(smem + PART_OFF);
    const uint32_t smb = smem_u32(smem);

    const int tid  = threadIdx.x;
    const int wid  = tid >> 5;
    const int lane = tid & 31;

    const int n0 = blockIdx.y * E_SUB;
    const int m0 = blockIdx.x * S_SUB;

    // ---- prologue: mbarriers, E/S fp16 staging, b1/w2, partials ----
    if (tid == 0) {
        #pragma unroll
        for (int s = 0; s < N_STAGES; ++s) {
            MBARRIER_INIT(smb + MBAR_OFF + s * 8, 64);        // full: 32 STS + 32 cp.async
            MBARRIER_INIT(smb + MBAR_OFF + 32 + s * 8, NCONS); // empty: 256 consumer arrives
        }
    }
    for (int i = tid; i < 4096; i += THREADS) {       // E -> fp16 [16][520]
        const int row = i >> 8, c = i & 255;
        const float2 v = *(const float2*)(E + (size_t)(n0 + row) * D_GLOB + c * 2);
        *(__half2*)(smE + row * 520 + c * 2) = __floats2half2_rn(v.x, v.y);
    }
    for (int i = tid; i < 2048; i += THREADS) {       // S -> fp16 [8][520]
        const int row = i >> 8, c = i & 255;
        const float2 v = *(const float2*)(S + (size_t)(m0 + row) * D_GLOB + c * 2);
        *(__half2*)(smS + row * 520 + c * 2) = __floats2half2_rn(v.x, v.y);
    }
    for (int i = tid; i < 512; i += THREADS) { smB1[i] = B1[i]; smW2[i] = W2[i]; }
    if (tid < P_TILE) smP[tid] = 0.f;
    __syncthreads();

    if (wid == 8) {
        // ================= PRODUCER (1 warp, 32 threads) =================
        const int c  = lane & 3;
        const int r  = lane >> 2;

        for (int p = 0; p < N_PHASES; ++p) {
            const int st   = p & 3;
            const int ph   = (p >> 2) & 1;
            const int slab = p & 15;
            const int pass = p >> 4;
            const uint32_t stg = smb + STAGE_OFF + st * STAGE_BYTES;

            MBARRIER_WAIT_PARITY(smb + MBAR_OFF + 32 + st * 8, ph ^ 1);  // wait empty

            // --- build A frags (fp16) into stage st: 16 pids = (mt_g<<1)|kt ---
            char* stA = smem + STAGE_OFF + st * STAGE_BYTES + A_IN_STAGE;
            #pragma unroll
            for (int pid = 0; pid < 16; ++pid) {
                const int mt_g = pid >> 1;
                const int kt   = pid & 1;
                const int row0 = mt_g * 2;
                const int kb   = slab * 32 + kt * 16 + c * 2;
                const __half2 e0  = *(const __half2*)(smE + row0 * 520 + kb);
                const __half2 e0b = *(const __half2*)(smE + row0 * 520 + kb + 8);
                const __half2 e1  = *(const __half2*)(smE + (row0 + 1) * 520 + kb);
                const __half2 e1b = *(const __half2*)(smE + (row0 + 1) * 520 + kb + 8);
                const __half2 s0  = *(const __half2*)(smS + r * 520 + kb);
                const __half2 s0b = *(const __half2*)(smS + r * 520 + kb + 8);
                uint4 v;
                v.x = h2_u32(__habs2(__hsub2(e0,  s0)));
                v.y = h2_u32(__habs2(__hsub2(e1,  s0)));
                v.z = h2_u32(__habs2(__hsub2(e0b, s0b)));
                v.w = h2_u32(__habs2(__hsub2(e1b, s0b)));
                *(uint4*)(stA + pid * 512 + lane * 16) = v;
            }
            MBARRIER_ARRIVE(smb + MBAR_OFF + st * 8);   // A visible (release)

            // --- B slab cp.async into stage st: [128 h][32 k] fp16, row 80 B ---
            #pragma unroll
            for (int j = 0; j < 16; ++j) {
                const int idx = lane + j * 32;          // 0..511
                const int h = idx >> 2, q = idx & 3;
                cpa16(stg + B_IN_STAGE + h * B_PADH * 2 + q * 16,
                      g_W1T + (size_t)(pass * H_TILE + h) * D_GLOB + slab * K_SLAB + q * 8);
            }
            CPASYNC_MBAR_ARRIVE(smb + MBAR_OFF + st * 8);  // arrives when cp.asyncs land
        }
    } else {
        // ============ CONSUMER (8 warps: 2 m-warps x 4 n-warps, 64x32 each) ============
        const int warp_m = wid & 1;       // 64-row half
        const int warp_n = wid >> 1;      // 32-col H quadrant
        const int c  = lane & 3;
        const int bn = warp_n * 32 + (lane >> 2);

        float acc[4][4][4];
        float psum[8];
        #pragma unroll
        for (int i = 0; i < 8; ++i) psum[i] = 0.f;

        for (int p = 0; p < N_PHASES; ++p) {
            const int st   = p & 3;
            const int ph   = (p >> 2) & 1;
            const int slab = p & 15;
            const int pass = p >> 4;

            MBARRIER_WAIT_PARITY(smb + MBAR_OFF + st * 8, ph);   // wait full

            if (slab == 0) {
                #pragma unroll
                for (int mt = 0; mt < 4; ++mt)
                    #pragma unroll
                    for (int nt = 0; nt < 4; ++nt)
                        #pragma unroll
                        for (int q = 0; q < 4; ++q) acc[mt][nt][q] = 0.f;
            }

            const char*   bA = smem + STAGE_OFF + st * STAGE_BYTES + A_IN_STAGE;
            const __half* bB = (const __half*)(smem + STAGE_OFF + st * STAGE_BYTES + B_IN_STAGE);
            #pragma unroll
            for (int kt = 0; kt < 2; ++kt) {
                uint4 af[4];
                #pragma unroll
                for (int mt = 0; mt < 4; ++mt)
                    af[mt] = *(const uint4*)(bA + (((warp_m * 4 + mt) * 2 + kt) * 32 + lane) * 16);
                uint32_t bq[4][2];
                const int kk = kt * 16 + c * 2;
                #pragma unroll
                for (int nt = 0; nt < 4; ++nt) {
                    bq[nt][0] = *(const uint32_t*)(bB + (bn + nt * 8) * B_PADH + kk);
                    bq[nt][1] = *(const uint32_t*)(bB + (bn + nt * 8) * B_PADH + kk + 8);
                }
                #pragma unroll
                for (int mt = 0; mt < 4; ++mt)
                    #pragma unroll
                    for (int nt = 0; nt < 4; ++nt) {
                        asm volatile(
                            "mma.sync.aligned.m16n8k16.row.col.f32.f16.f16.f32 "
                            "{%0,%1,%2,%3}, {%4,%5,%6,%7}, {%8,%9}, {%0,%1,%2,%3};\n"
                            : "+f"(acc[mt][nt][0]), "+f"(acc[mt][nt][1]),
                              "+f"(acc[mt][nt][2]), "+f"(acc[mt][nt][3])
                            : "r"(af[mt].x), "r"(af[mt].y), "r"(af[mt].z), "r"(af[mt].w),
                              "r"(bq[nt][0]), "r"(bq[nt][1]));
                    }
            }
            MBARRIER_ARRIVE(smb + MBAR_OFF + 32 + st * 8);   // stage consumed

            if (slab == 15) {
                #pragma unroll
                for (int mt = 0; mt < 4; ++mt)
                    #pragma unroll
                    for (int nt = 0; nt < 4; ++nt) {
                        const int jg = pass * H_TILE + warp_n * 32 + nt * 8 + c * 2;
                        const float b1a = smB1[jg], b1b = smB1[jg + 1];
                        const float w2a = smW2[jg], w2b = smW2[jg + 1];
                        const float h0 = fmaxf(acc[mt][nt][0] + b1a, 0.f);
                        const float h1 = fmaxf(acc[mt][nt][1] + b1b, 0.f);
                        const float h2 = fmaxf(acc[mt][nt][2] + b1a, 0.f);
                        const float h3 = fmaxf(acc[mt][nt][3] + b1b, 0.f);
                        psum[mt * 2 + 0] += h0 * w2a + h1 * w2b;
                        psum[mt * 2 + 1] += h2 * w2a + h3 * w2b;
                    }
            }
        }

        // reduce across quad (k-cols of frag), then across n-warps via smem atomics
        #pragma unroll
        for (int i = 0; i < 8; ++i) {
            psum[i] += __shfl_xor_sync(0xffffffffu, psum[i], 1);
            psum[i] += __shfl_xor_sync(0xffffffffu, psum[i], 2);
        }
        if (c == 0) {
            const int r = lane >> 2;
            #pragma unroll
            for (int mt = 0; mt < 4; ++mt) {
                atomicAdd(&smP[warp_m * 64 + mt * 16 + r],     psum[mt * 2 + 0]);
                atomicAdd(&smP[warp_m * 64 + mt * 16 + r + 8], psum[mt * 2 + 1]);
            }
        }
    }

    __syncthreads();
    if (tid < P_TILE) {
        const float logit = smP[tid] + B2[0];
        const int n = n0 + (tid >> 3);
        const int m = m0 + (tid & 7);
        out[(size_t)n * M_GLOB + m] = 1.f / (1.f + expf(-logit));
    }
}

extern "C" void kernel_launch(void* const* d_in, const int* in_sizes, int n_in,
                              void* d_out, int out_size)
{
    const float* E  = (const float*)d_in[0];
    const float* S  = (const float*)d_in[1];
    const float* W1 = (const float*)d_in[2];
    const float* B1 = (const float*)d_in[3];
    const float* W2 = (const float*)d_in[4];
    const float* B2 = (const float*)d_in[5];
    float* out = (float*)d_out;

    convert_w1_kernel<<<dim3(16, 16), dim3(32, 8)>>>(W1);

    cudaFuncSetAttribute(support_ws_kernel,
                         cudaFuncAttributeMaxDynamicSharedMemorySize, SMEM_BYTES);
    dim3 grid(M_GLOB / S_SUB, N_GLOB / E_SUB);   // (128, 16) = 2048 CTAs
    support_ws_kernel<<<grid, THREADS, SMEM_BYTES>>>(E, S, B1, W2, B2, out);
}

// round 12
// speedup vs baseline: 2.1957x; 1.0845x over previous
#include <cuda_runtime.h>
#include <cuda_fp16.h>
#include <cstdint>
#include <math.h>

// Problem constants
#define N_GLOB 256
#define M_GLOB 1024
#define D_GLOB 512
#define H_GLOB 512

// Tiling: 256 pairs (32e x 8s) per CTA, H in 4 passes of 128, K slab 32
#define E_SUB    32
#define S_SUB    8
#define P_TILE   256
#define H_TILE   128
#define K_SLAB   32
#define N_PHASES 64           // 4 passes * 16 slabs
#define THREADS  512          // 16 warps: 8 m-warps x 2 n-warps, no specialization

// SMEM layout (byte offsets)
#define B1_OFF   0            // 512 f32
#define W2_OFF   2048         // 512 f32
#define PART_OFF 4096         // 256 f32
#define ES_OFF   5120         // [32][520] half (33280 B)
#define SS_OFF   38400        // [8][520]  half (8320 B)
#define STG_OFF  46720        // 4 x 10240 B  (B ring: [128 rows][40 halfs])
#define STG_BYTES 10240
#define SMEM_BYTES 87680

#define B_PADH   40           // halfs per B row (32 data + 8 pad)

__device__ static __half g_W1T[H_GLOB * D_GLOB];   // W1 transposed [h][k], fp16

__device__ __forceinline__ uint32_t smem_u32(const void* p) {
    uint32_t a;
    asm("{ .reg .u64 t; cvta.to.shared.u64 t, %1; cvt.u32.u64 %0, t; }" : "=r"(a) : "l"(p));
    return a;
}
__device__ __forceinline__ void cpa16(uint32_t s, const void* g) {
    asm volatile("cp.async.cg.shared.global [%0], [%1], 16;" :: "r"(s), "l"(g));
}
#define CP_COMMIT() asm volatile("cp.async.commit_group;" ::: "memory")
#define CP_WAIT2()  asm volatile("cp.async.wait_group 2;" ::: "memory")

__device__ __forceinline__ uint32_t h2_u32(__half2 h) {
    uint32_t u;
    __builtin_memcpy(&u, &h, 4);
    return u;
}

// ---- pre-kernel: W1 [D][H] f32  ->  g_W1T [H][D] fp16 ----
__global__ void convert_w1_kernel(const float* __restrict__ W1) {
    __shared__ float tile[32][33];
    const int kx = blockIdx.x * 32;
    const int hx = blockIdx.y * 32;
    const int x = threadIdx.x, y = threadIdx.y;   // 32 x 8
    #pragma unroll
    for (int i = 0; i < 32; i += 8)
        tile[y + i][x] = W1[(size_t)(kx + y + i) * H_GLOB + hx + x];
    __syncthreads();
    #pragma unroll
    for (int i = 0; i < 32; i += 8)
        g_W1T[(size_t)(hx + y + i) * D_GLOB + kx + x] = __float2half(tile[x][y + i]);
}

__global__ void __launch_bounds__(THREADS, 1)
support_sp_kernel(const float* __restrict__ E,   // [N, D]
                  const float* __restrict__ S,   // [M, D]
                  const float* __restrict__ B1,  // [H]
                  const float* __restrict__ W2,  // [H]
                  const float* __restrict__ B2,  // [1]
                  float* __restrict__ out)       // [N, M]
{
    extern __shared__ char smem[];
    __half* smE  = (__half*)(smem + ES_OFF);
    __half* smS  = (__half*)(smem + SS_OFF);
    float*  smB1 = (float*)(smem + B1_OFF);
    float*  smW2 = (float*)(smem + W2_OFF);
    float*  smP  = (float*)(smem + PART_OFF);
    const uint32_t smb = smem_u32(smem);

    const int tid  = threadIdx.x;
    const int wid  = tid >> 5;
    const int lane = tid & 31;

    const int n0 = blockIdx.y * E_SUB;
    const int m0 = blockIdx.x * S_SUB;

    // B prefetch helper: phase pf -> stage pf&3; each thread copies one 16B chunk
    const int bh = tid >> 2, bq = tid & 3;      // row 0..127, quarter 0..3
    auto issueB = [&](int pf) {
        cpa16(smb + STG_OFF + (pf & 3) * STG_BYTES + bh * (B_PADH * 2) + bq * 16,
              g_W1T + (size_t)((pf >> 4) * H_TILE + bh) * D_GLOB + (pf & 15) * K_SLAB + bq * 8);
    };

    // issue B for phases 0 and 1 immediately (overlaps with E/S staging)
    issueB(0); CP_COMMIT();
    issueB(1); CP_COMMIT();

    // ---- stage E/S as fp16 [row][520]; b1/w2/partials ----
    #pragma unroll
    for (int i = tid; i < 8192; i += THREADS) {       // E: 32 rows x 256 half2
        const int row = i >> 8, cc = i & 255;
        const float2 v = *(const float2*)(E + (size_t)(n0 + row) * D_GLOB + cc * 2);
        *(__half2*)(smE + row * 520 + cc * 2) = __floats2half2_rn(v.x, v.y);
    }
    #pragma unroll
    for (int i = tid; i < 2048; i += THREADS) {       // S: 8 rows x 256 half2
        const int row = i >> 8, cc = i & 255;
        const float2 v = *(const float2*)(S + (size_t)(m0 + row) * D_GLOB + cc * 2);
        *(__half2*)(smS + row * 520 + cc * 2) = __floats2half2_rn(v.x, v.y);
    }
    if (tid < 512) { smB1[tid] = B1[tid]; smW2[tid] = W2[tid]; }
    if (tid < P_TILE) smP[tid] = 0.f;
    __syncthreads();

    const int warp_m = wid & 7;       // 32-row block (2 x 16-row tiles)
    const int warp_n = wid >> 3;      // 64-col H half
    const int c = lane & 3;
    const int r = lane >> 2;
    const int bn = warp_n * 64 + r;

    float acc[2][8][4];
    float psum[4] = {0.f, 0.f, 0.f, 0.f};

    for (int p = 0; p < N_PHASES; ++p) {
        const int st   = p & 3;
        const int slab = p & 15;
        const int pass = p >> 4;

        // prefetch phase p+2 (overwrites buffer of phase p-2: protected by
        // the phase p-1 barrier). Always commit to keep group count aligned.
        if (p + 2 < N_PHASES) issueB(p + 2);
        CP_COMMIT();
        CP_WAIT2();          // group for phase p complete (<=2 pending)
        __syncthreads();     // visibility of stage st to all warps

        if (slab == 0) {
            #pragma unroll
            for (int mt = 0; mt < 2; ++mt)
                #pragma unroll
                for (int nt = 0; nt < 8; ++nt)
                    #pragma unroll
                    for (int q = 0; q < 4; ++q) acc[mt][nt][q] = 0.f;
        }

        const __half* bB = (const __half*)(smem + STG_OFF + st * STG_BYTES);
        #pragma unroll
        for (int kt = 0; kt < 2; ++kt) {
            const int kb = slab * 32 + kt * 16 + c * 2;
            // ---- A fragment in registers: |e - s| for this warp's 32 rows ----
            uint32_t a[2][4];
            #pragma unroll
            for (int mt = 0; mt < 2; ++mt) {
                const int er = (warp_m * 2 + mt) * 2;       // e-row pair base
                const __half2 e0  = *(const __half2*)(smE + er * 520 + kb);
                const __half2 e0b = *(const __half2*)(smE + er * 520 + kb + 8);
                const __half2 e1  = *(const __half2*)(smE + (er + 1) * 520 + kb);
                const __half2 e1b = *(const __half2*)(smE + (er + 1) * 520 + kb + 8);
                const __half2 s0  = *(const __half2*)(smS + r * 520 + kb);
                const __half2 s0b = *(const __half2*)(smS + r * 520 + kb + 8);
                a[mt][0] = h2_u32(__habs2(__hsub2(e0,  s0)));
                a[mt][1] = h2_u32(__habs2(__hsub2(e1,  s0)));
                a[mt][2] = h2_u32(__habs2(__hsub2(e0b, s0b)));
                a[mt][3] = h2_u32(__habs2(__hsub2(e1b, s0b)));
            }
            const int kk = kt * 16 + c * 2;
            #pragma unroll
            for (int nt = 0; nt < 8; ++nt) {
                const uint32_t b0 = *(const uint32_t*)(bB + (bn + nt * 8) * B_PADH + kk);
                const uint32_t b1 = *(const uint32_t*)(bB + (bn + nt * 8) * B_PADH + kk + 8);
                #pragma unroll
                for (int mt = 0; mt < 2; ++mt) {
                    asm volatile(
                        "mma.sync.aligned.m16n8k16.row.col.f32.f16.f16.f32 "
                        "{%0,%1,%2,%3}, {%4,%5,%6,%7}, {%8,%9}, {%0,%1,%2,%3};\n"
                        : "+f"(acc[mt][nt][0]), "+f"(acc[mt][nt][1]),
                          "+f"(acc[mt][nt][2]), "+f"(acc[mt][nt][3])
                        : "r"(a[mt][0]), "r"(a[mt][1]), "r"(a[mt][2]), "r"(a[mt][3]),
                          "r"(b0), "r"(b1));
                }
            }
        }

        // ---- pass epilogue: relu(+b1) * w2, fold into psum ----
        if (slab == 15) {
            #pragma unroll
            for (int mt = 0; mt < 2; ++mt)
                #pragma unroll
                for (int nt = 0; nt < 8; ++nt) {
                    const int jg = pass * H_TILE + warp_n * 64 + nt * 8 + c * 2;
                    const float b1a = smB1[jg], b1b = smB1[jg + 1];
                    const float w2a = smW2[jg], w2b = smW2[jg + 1];
                    const float h0 = fmaxf(acc[mt][nt][0] + b1a, 0.f);
                    const float h1 = fmaxf(acc[mt][nt][1] + b1b, 0.f);
                    const float h2 = fmaxf(acc[mt][nt][2] + b1a, 0.f);
                    const float h3 = fmaxf(acc[mt][nt][3] + b1b, 0.f);
                    psum[mt * 2 + 0] += h0 * w2a + h1 * w2b;
                    psum[mt * 2 + 1] += h2 * w2a + h3 * w2b;
                }
        }
    }

    // ---- reduce across quad (k-cols of frag), then across 2 n-warps ----
    #pragma unroll
    for (int i = 0; i < 4; ++i) {
        psum[i] += __shfl_xor_sync(0xffffffffu, psum[i], 1);
        psum[i] += __shfl_xor_sync(0xffffffffu, psum[i], 2);
    }
    if (c == 0) {
        #pragma unroll
        for (int mt = 0; mt < 2; ++mt) {
            atomicAdd(&smP[warp_m * 32 + mt * 16 + r],     psum[mt * 2 + 0]);
            atomicAdd(&smP[warp_m * 32 + mt * 16 + r + 8], psum[mt * 2 + 1]);
        }
    }
    __syncthreads();

    if (tid < P_TILE) {
        const float logit = smP[tid] + B2[0];
        const int n = n0 + (tid >> 3);
        const int m = m0 + (tid & 7);
        out[(size_t)n * M_GLOB + m] = 1.f / (1.f + expf(-logit));
    }
}

extern "C" void kernel_launch(void* const* d_in, const int* in_sizes, int n_in,
                              void* d_out, int out_size)
{
    const float* E  = (const float*)d_in[0];
    const float* S  = (const float*)d_in[1];
    const float* W1 = (const float*)d_in[2];
    const float* B1 = (const float*)d_in[3];
    const float* W2 = (const float*)d_in[4];
    const float* B2 = (const float*)d_in[5];
    float* out = (float*)d_out;

    convert_w1_kernel<<<dim3(16, 16), dim3(32, 8)>>>(W1);

    cudaFuncSetAttribute(support_sp_kernel,
                         cudaFuncAttributeMaxDynamicSharedMemorySize, SMEM_BYTES);
    dim3 grid(M_GLOB / S_SUB, N_GLOB / E_SUB);   // (128, 8) = 1024 CTAs
    support_sp_kernel<<<grid, THREADS, SMEM_BYTES>>>(E, S, B1, W2, B2, out);
}

// round 14
// speedup vs baseline: 2.6669x; 1.2146x over previous
#include <cuda_runtime.h>
#include <cuda_fp16.h>
#include <cstdint>
#include <math.h>

// Problem constants
#define N_GLOB 256
#define M_GLOB 1024
#define D_GLOB 512
#define H_GLOB 512

// Tiling: 256 pairs (32e x 8s) per CTA, H in 4 passes of 128, K slab 32
#define E_SUB    32
#define S_SUB    8
#define P_TILE   256
#define H_TILE   128
#define K_SLAB   32
#define N_PHASES 64           // 4 passes * 16 slabs
#define THREADS  512          // 16 warps: 8 m-warps x 2 n-warps

// SMEM layout (byte offsets)
#define B1_OFF   0            // 512 f32
#define W2_OFF   2048         // 512 f32
#define PART_OFF 4096         // 256 f32
#define ES_OFF   5120         // [32][528] half (33792 B)  k-interleaved
#define SS_OFF   38912        // [8][528]  half (8448 B)   k-interleaved
#define STG_OFF  47360        // 4 x 8192 B  (B frag ring)
#define STG_BYTES 8192
#define SMEM_BYTES 80128

#define ES_STRIDE 528         // halfs per row

// W1 in fragment-major layout: [phase(64)][kt(2)][hpair(8)][lane(32)] uint4
__device__ static uint4 g_W1F[N_PHASES * 512];

__device__ __forceinline__ uint32_t smem_u32(const void* p) {
    uint32_t a;
    asm("{ .reg .u64 t; cvta.to.shared.u64 t, %1; cvt.u32.u64 %0, t; }" : "=r"(a) : "l"(p));
    return a;
}
__device__ __forceinline__ void cpa16(uint32_t s, const void* g) {
    asm volatile("cp.async.cg.shared.global [%0], [%1], 16;" :: "r"(s), "l"(g));
}
#define CP_COMMIT() asm volatile("cp.async.commit_group;" ::: "memory")
#define CP_WAIT0()  asm volatile("cp.async.wait_group 0;" ::: "memory")

__device__ __forceinline__ uint32_t h2_u32(__half2 h) {
    uint32_t u; __builtin_memcpy(&u, &h, 4); return u;
}
__device__ __forceinline__ __half2 u32_h2(uint32_t u) {
    __half2 h; __builtin_memcpy(&h, &u, 4); return h;
}
__device__ __forceinline__ uint32_t habs_sub(uint32_t e, uint32_t s) {
    return h2_u32(__habs2(__hsub2(u32_h2(e), u32_h2(s))));
}

// ---- pre-kernel: W1 [D][H] f32 -> g_W1F fragment-major fp16 ----
// thread t -> one uint4: t = ((p*2 + kt)*8 + hp)*32 + lane
__global__ void convert_w1f_kernel(const float* __restrict__ W1) {
    const int t    = blockIdx.x * 256 + threadIdx.x;   // 0..32767
    const int lane = t & 31;
    const int hp   = (t >> 5) & 7;
    const int kt   = (t >> 8) & 1;
    const int p    = t >> 9;
    const int pass = p >> 4, slab = p & 15;
    const int kb   = slab * 32 + kt * 16 + (lane & 3) * 2;
    uint4 v;
    uint32_t w[4];
    #pragma unroll
    for (int j = 0; j < 2; ++j) {
        const int n = pass * 128 + hp * 16 + j * 8 + (lane >> 2);
        const __half2 b0 = __floats2half2_rn(W1[(size_t)kb * H_GLOB + n],
                                             W1[(size_t)(kb + 1) * H_GLOB + n]);
        const __half2 b1 = __floats2half2_rn(W1[(size_t)(kb + 8) * H_GLOB + n],
                                             W1[(size_t)(kb + 9) * H_GLOB + n]);
        w[j * 2 + 0] = h2_u32(b0);
        w[j * 2 + 1] = h2_u32(b1);
    }
    v.x = w[0]; v.y = w[1]; v.z = w[2]; v.w = w[3];
    g_W1F[t] = v;
}

__global__ void __launch_bounds__(THREADS, 1)
support_sp_kernel(const float* __restrict__ E,   // [N, D]
                  const float* __restrict__ S,   // [M, D]
                  const float* __restrict__ B1,  // [H]
                  const float* __restrict__ W2,  // [H]
                  const float* __restrict__ B2,  // [1]
                  float* __restrict__ out)       // [N, M]
{
    extern __shared__ char smem[];
    __half* smE  = (__half*)(smem + ES_OFF);
    __half* smS  = (__half*)(smem + SS_OFF);
    float*  smB1 = (float*)(smem + B1_OFF);
    float*  smW2 = (float*)(smem + W2_OFF);
    float*  smP  = (float*)(smem + PART_OFF);
    const uint32_t smb = smem_u32(smem);

    const int tid  = threadIdx.x;
    const int wid  = tid >> 5;
    const int lane = tid & 31;

    const int n0 = blockIdx.y * E_SUB;
    const int m0 = blockIdx.x * S_SUB;

    // B prefetch: phase pf -> stage pf&3; 512 threads x 16 B = 8192 B
    auto issueB = [&](int pf) {
        cpa16(smb + STG_OFF + (pf & 3) * STG_BYTES + tid * 16, g_W1F + pf * 512 + tid);
    };

    issueB(0); CP_COMMIT();
    issueB(1); CP_COMMIT();

    // ---- stage E/S as fp16, k-interleaved: block b of 8 half2, j -> (j<4 ? 2j : 2(j-4)+1)
    #pragma unroll
    for (int i = tid; i < 8192; i += THREADS) {       // E: 32 rows x 256 half2
        const int row = i >> 8, c2 = i & 255;
        const float2 v = *(const float2*)(E + (size_t)(n0 + row) * D_GLOB + c2 * 2);
        const int b = c2 >> 3, j = c2 & 7;
        const int nc2 = b * 8 + (j < 4 ? 2 * j : 2 * (j - 4) + 1);
        *(__half2*)(smE + row * ES_STRIDE + nc2 * 2) = __floats2half2_rn(v.x, v.y);
    }
    #pragma unroll
    for (int i = tid; i < 2048; i += THREADS) {       // S: 8 rows x 256 half2
        const int row = i >> 8, c2 = i & 255;
        const float2 v = *(const float2*)(S + (size_t)(m0 + row) * D_GLOB + c2 * 2);
        const int b = c2 >> 3, j = c2 & 7;
        const int nc2 = b * 8 + (j < 4 ? 2 * j : 2 * (j - 4) + 1);
        *(__half2*)(smS + row * ES_STRIDE + nc2 * 2) = __floats2half2_rn(v.x, v.y);
    }
    if (tid < 512) { smB1[tid] = B1[tid]; smW2[tid] = W2[tid]; }
    if (tid < P_TILE) smP[tid] = 0.f;
    __syncthreads();

    const int warp_m = wid & 7;       // 32-row block (2 x 16-row tiles)
    const int warp_n = wid >> 3;      // 64-col H half
    const int c = lane & 3;
    const int r = lane >> 2;

    float acc[2][8][4];
    float psum[4] = {0.f, 0.f, 0.f, 0.f};

    auto compute = [&](int p) {
        const int st   = p & 3;
        const int slab = p & 15;
        const int pass = p >> 4;

        if (slab == 0) {
            #pragma unroll
            for (int mt = 0; mt < 2; ++mt)
                #pragma unroll
                for (int nt = 0; nt < 8; ++nt)
                    #pragma unroll
                    for (int q = 0; q < 4; ++q) acc[mt][nt][q] = 0.f;
        }

        const uint4* bB = (const uint4*)(smem + STG_OFF + st * STG_BYTES);
        #pragma unroll
        for (int kt = 0; kt < 2; ++kt) {
            const int bh = (slab * 2 + kt) * 16 + c * 4;   // half offset within row
            // ---- A fragments: 5 LDS.64 ----
            const uint2 us = *(const uint2*)(smS + r * ES_STRIDE + bh);
            uint32_t a[2][4];
            #pragma unroll
            for (int mt = 0; mt < 2; ++mt) {
                const int er = (warp_m * 2 + mt) * 2;
                const uint2 ue0 = *(const uint2*)(smE + er * ES_STRIDE + bh);
                const uint2 ue1 = *(const uint2*)(smE + (er + 1) * ES_STRIDE + bh);
                a[mt][0] = habs_sub(ue0.x, us.x);
                a[mt][1] = habs_sub(ue1.x, us.x);
                a[mt][2] = habs_sub(ue0.y, us.y);
                a[mt][3] = habs_sub(ue1.y, us.y);
            }
            // ---- B fragments: 4 LDS.128, each covers 2 nt ----
            #pragma unroll
            for (int hl = 0; hl < 4; ++hl) {
                const uint4 v = bB[kt * 256 + (warp_n * 4 + hl) * 32 + lane];
                const int nt0 = hl * 2, nt1 = hl * 2 + 1;
                #pragma unroll
                for (int mt = 0; mt < 2; ++mt) {
                    asm volatile(
                        "mma.sync.aligned.m16n8k16.row.col.f32.f16.f16.f32 "
                        "{%0,%1,%2,%3}, {%4,%5,%6,%7}, {%8,%9}, {%0,%1,%2,%3};\n"
                        : "+f"(acc[mt][nt0][0]), "+f"(acc[mt][nt0][1]),
                          "+f"(acc[mt][nt0][2]), "+f"(acc[mt][nt0][3])
                        : "r"(a[mt][0]), "r"(a[mt][1]), "r"(a[mt][2]), "r"(a[mt][3]),
                          "r"(v.x), "r"(v.y));
                }
                #pragma unroll
                for (int mt = 0; mt < 2; ++mt) {
                    asm volatile(
                        "mma.sync.aligned.m16n8k16.row.col.f32.f16.f16.f32 "
                        "{%0,%1,%2,%3}, {%4,%5,%6,%7}, {%8,%9}, {%0,%1,%2,%3};\n"
                        : "+f"(acc[mt][nt1][0]), "+f"(acc[mt][nt1][1]),
                          "+f"(acc[mt][nt1][2]), "+f"(acc[mt][nt1][3])
                        : "r"(a[mt][0]), "r"(a[mt][1]), "r"(a[mt][2]), "r"(a[mt][3]),
                          "r"(v.z), "r"(v.w));
                }
            }
        }

        if (slab == 15) {
            #pragma unroll
            for (int mt = 0; mt < 2; ++mt)
                #pragma unroll
                for (int nt = 0; nt < 8; ++nt) {
                    const int jg = pass * H_TILE + warp_n * 64 + nt * 8 + c * 2;
                    const float b1a = smB1[jg], b1b = smB1[jg + 1];
                    const float w2a = smW2[jg], w2b = smW2[jg + 1];
                    const float h0 = fmaxf(acc[mt][nt][0] + b1a, 0.f);
                    const float h1 = fmaxf(acc[mt][nt][1] + b1b, 0.f);
                    const float h2 = fmaxf(acc[mt][nt][2] + b1a, 0.f);
                    const float h3 = fmaxf(acc[mt][nt][3] + b1b, 0.f);
                    psum[mt * 2 + 0] += h0 * w2a + h1 * w2b;
                    psum[mt * 2 + 1] += h2 * w2a + h3 * w2b;
                }
        }
    };

    // paired phases: one wait + one sync per 2 phases (ring distance 4 keeps
    // prefetch writes behind the sync that retired their stage's last reader)
    for (int pp = 0; pp < N_PHASES; pp += 2) {
        CP_WAIT0();          // my copies for phases pp, pp+1 complete
        __syncthreads();     // publish them; all readers of stages (pp+2)&3, (pp+3)&3 done
        if (pp + 2 < N_PHASES) { issueB(pp + 2); CP_COMMIT(); }
        if (pp + 3 < N_PHASES) { issueB(pp + 3); CP_COMMIT(); }
        compute(pp);
        compute(pp + 1);
    }

    // ---- reduce across quad (k-cols of frag), then across 2 n-warps ----
    #pragma unroll
    for (int i = 0; i < 4; ++i) {
        psum[i] += __shfl_xor_sync(0xffffffffu, psum[i], 1);
        psum[i] += __shfl_xor_sync(0xffffffffu, psum[i], 2);
    }
    if (c == 0) {
        #pragma unroll
        for (int mt = 0; mt < 2; ++mt) {
            atomicAdd(&smP[warp_m * 32 + mt * 16 + r],     psum[mt * 2 + 0]);
            atomicAdd(&smP[warp_m * 32 + mt * 16 + r + 8], psum[mt * 2 + 1]);
        }
    }
    __syncthreads();

    if (tid < P_TILE) {
        const float logit = smP[tid] + B2[0];
        const int n = n0 + (tid >> 3);
        const int m = m0 + (tid & 7);
        out[(size_t)n * M_GLOB + m] = 1.f / (1.f + expf(-logit));
    }
}

extern "C" void kernel_launch(void* const* d_in, const int* in_sizes, int n_in,
                              void* d_out, int out_size)
{
    const float* E  = (const float*)d_in[0];
    const float* S  = (const float*)d_in[1];
    const float* W1 = (const float*)d_in[2];
    const float* B1 = (const float*)d_in[3];
    const float* W2 = (const float*)d_in[4];
    const float* B2 = (const float*)d_in[5];
    float* out = (float*)d_out;

    convert_w1f_kernel<<<128, 256>>>(W1);

    cudaFuncSetAttribute(support_sp_kernel,
                         cudaFuncAttributeMaxDynamicSharedMemorySize, SMEM_BYTES);
    dim3 grid(M_GLOB / S_SUB, N_GLOB / E_SUB);   // (128, 8) = 1024 CTAs
    support_sp_kernel<<<grid, THREADS, SMEM_BYTES>>>(E, S, B1, W2, B2, out);
}

// round 15
// speedup vs baseline: 2.9886x; 1.1206x over previous
#include <cuda_runtime.h>
#include <cuda_fp16.h>
#include <cstdint>
#include <math.h>

// Problem constants
#define N_GLOB 256
#define M_GLOB 1024
#define D_GLOB 512
#define H_GLOB 512

// Tiling: 256 pairs (32e x 8s) per CTA, H in 4 passes of 128, K slab 32
#define E_SUB    32
#define S_SUB    8
#define P_TILE   256
#define H_TILE   128
#define K_SLAB   32
#define N_PHASES 64           // 4 passes * 16 slabs
#define THREADS  512          // 16 warps: 8 m-warps x 2 n-warps

// SMEM layout (byte offsets)
#define B1_OFF   0            // 512 f32
#define W2_OFF   2048         // 512 f32
#define PART_OFF 4096         // 256 f32
#define ES_OFF   5120         // [32][528] half (33792 B)  k-interleaved
#define SS_OFF   38912        // [8][528]  half (8448 B)   k-interleaved
#define SMEM_BYTES 47360

#define ES_STRIDE 528         // halfs per row

// W1 in fragment-major layout: [phase(64)][kt(2)][hpair(8)][lane(32)] uint4
__device__ static uint4 g_W1F[N_PHASES * 512];

__device__ __forceinline__ uint32_t h2_u32(__half2 h) {
    uint32_t u; __builtin_memcpy(&u, &h, 4); return u;
}
__device__ __forceinline__ __half2 u32_h2(uint32_t u) {
    __half2 h; __builtin_memcpy(&h, &u, 4); return h;
}
__device__ __forceinline__ uint32_t habs_sub(uint32_t e, uint32_t s) {
    return h2_u32(__habs2(__hsub2(u32_h2(e), u32_h2(s))));
}

// ---- pre-kernel: W1 [D][H] f32 -> g_W1F fragment-major fp16 ----
// thread t -> one uint4: t = ((p*2 + kt)*8 + hp)*32 + lane
__global__ void convert_w1f_kernel(const float* __restrict__ W1) {
    const int t    = blockIdx.x * 256 + threadIdx.x;   // 0..32767
    const int lane = t & 31;
    const int hp   = (t >> 5) & 7;
    const int kt   = (t >> 8) & 1;
    const int p    = t >> 9;
    const int pass = p >> 4, slab = p & 15;
    const int kb   = slab * 32 + kt * 16 + (lane & 3) * 2;
    uint4 v;
    uint32_t w[4];
    #pragma unroll
    for (int j = 0; j < 2; ++j) {
        const int n = pass * 128 + hp * 16 + j * 8 + (lane >> 2);
        const __half2 b0 = __floats2half2_rn(W1[(size_t)kb * H_GLOB + n],
                                             W1[(size_t)(kb + 1) * H_GLOB + n]);
        const __half2 b1 = __floats2half2_rn(W1[(size_t)(kb + 8) * H_GLOB + n],
                                             W1[(size_t)(kb + 9) * H_GLOB + n]);
        w[j * 2 + 0] = h2_u32(b0);
        w[j * 2 + 1] = h2_u32(b1);
    }
    v.x = w[0]; v.y = w[1]; v.z = w[2]; v.w = w[3];
    g_W1F[t] = v;
}

__global__ void __launch_bounds__(THREADS, 1)
support_sp_kernel(const float* __restrict__ E,   // [N, D]
                  const float* __restrict__ S,   // [M, D]
                  const float* __restrict__ B1,  // [H]
                  const float* __restrict__ W2,  // [H]
                  const float* __restrict__ B2,  // [1]
                  float* __restrict__ out)       // [N, M]
{
    extern __shared__ char smem[];
    __half* smE  = (__half*)(smem + ES_OFF);
    __half* smS  = (__half*)(smem + SS_OFF);
    float*  smB1 = (float*)(smem + B1_OFF);
    float*  smW2 = (float*)(smem + W2_OFF);
    float*  smP  = (float*)(smem + PART_OFF);

    const int tid  = threadIdx.x;
    const int wid  = tid >> 5;
    const int lane = tid & 31;

    const int n0 = blockIdx.y * E_SUB;
    const int m0 = blockIdx.x * S_SUB;

    // ---- stage E/S as fp16, k-interleaved: block b of 8 half2, j -> (j<4 ? 2j : 2(j-4)+1)
    #pragma unroll
    for (int i = tid; i < 8192; i += THREADS) {       // E: 32 rows x 256 half2
        const int row = i >> 8, c2 = i & 255;
        const float2 v = *(const float2*)(E + (size_t)(n0 + row) * D_GLOB + c2 * 2);
        const int b = c2 >> 3, j = c2 & 7;
        const int nc2 = b * 8 + (j < 4 ? 2 * j : 2 * (j - 4) + 1);
        *(__half2*)(smE + row * ES_STRIDE + nc2 * 2) = __floats2half2_rn(v.x, v.y);
    }
    #pragma unroll
    for (int i = tid; i < 2048; i += THREADS) {       // S: 8 rows x 256 half2
        const int row = i >> 8, c2 = i & 255;
        const float2 v = *(const float2*)(S + (size_t)(m0 + row) * D_GLOB + c2 * 2);
        const int b = c2 >> 3, j = c2 & 7;
        const int nc2 = b * 8 + (j < 4 ? 2 * j : 2 * (j - 4) + 1);
        *(__half2*)(smS + row * ES_STRIDE + nc2 * 2) = __floats2half2_rn(v.x, v.y);
    }
    if (tid < 512) { smB1[tid] = B1[tid]; smW2[tid] = W2[tid]; }
    if (tid < P_TILE) smP[tid] = 0.f;
    __syncthreads();          // the ONLY barrier before the final reduction

    const int warp_m = wid & 7;       // 32-row block (2 x 16-row tiles)
    const int warp_n = wid >> 3;      // 64-col H half
    const int c = lane & 3;
    const int r = lane >> 2;

    float acc[2][8][4];
    float psum[4] = {0.f, 0.f, 0.f, 0.f};

    // free-running mainloop: B straight from global fragments, no cross-warp sync
    for (int p = 0; p < N_PHASES; ++p) {
        const int slab = p & 15;
        const int pass = p >> 4;

        if (slab == 0) {
            #pragma unroll
            for (int mt = 0; mt < 2; ++mt)
                #pragma unroll
                for (int nt = 0; nt < 8; ++nt)
                    #pragma unroll
                    for (int q = 0; q < 4; ++q) acc[mt][nt][q] = 0.f;
        }

        const uint4* __restrict__ gB = g_W1F + p * 512;
        #pragma unroll
        for (int kt = 0; kt < 2; ++kt) {
            const int bh = (slab * 2 + kt) * 16 + c * 4;   // half offset within row
            // ---- A fragments: 5 LDS.64 + 16 hsub/habs ----
            const uint2 us = *(const uint2*)(smS + r * ES_STRIDE + bh);
            uint32_t a[2][4];
            #pragma unroll
            for (int mt = 0; mt < 2; ++mt) {
                const int er = (warp_m * 2 + mt) * 2;
                const uint2 ue0 = *(const uint2*)(smE + er * ES_STRIDE + bh);
                const uint2 ue1 = *(const uint2*)(smE + (er + 1) * ES_STRIDE + bh);
                a[mt][0] = habs_sub(ue0.x, us.x);
                a[mt][1] = habs_sub(ue1.x, us.x);
                a[mt][2] = habs_sub(ue0.y, us.y);
                a[mt][3] = habs_sub(ue1.y, us.y);
            }
            // ---- B fragments: 4 LDG.128 (L1/L2-cached), each covers 2 nt ----
            #pragma unroll
            for (int hl = 0; hl < 4; ++hl) {
                const uint4 v = __ldg(gB + kt * 256 + (warp_n * 4 + hl) * 32 + lane);
                const int nt0 = hl * 2, nt1 = hl * 2 + 1;
                #pragma unroll
                for (int mt = 0; mt < 2; ++mt) {
                    asm volatile(
                        "mma.sync.aligned.m16n8k16.row.col.f32.f16.f16.f32 "
                        "{%0,%1,%2,%3}, {%4,%5,%6,%7}, {%8,%9}, {%0,%1,%2,%3};\n"
                        : "+f"(acc[mt][nt0][0]), "+f"(acc[mt][nt0][1]),
                          "+f"(acc[mt][nt0][2]), "+f"(acc[mt][nt0][3])
                        : "r"(a[mt][0]), "r"(a[mt][1]), "r"(a[mt][2]), "r"(a[mt][3]),
                          "r"(v.x), "r"(v.y));
                }
                #pragma unroll
                for (int mt = 0; mt < 2; ++mt) {
                    asm volatile(
                        "mma.sync.aligned.m16n8k16.row.col.f32.f16.f16.f32 "
                        "{%0,%1,%2,%3}, {%4,%5,%6,%7}, {%8,%9}, {%0,%1,%2,%3};\n"
                        : "+f"(acc[mt][nt1][0]), "+f"(acc[mt][nt1][1]),
                          "+f"(acc[mt][nt1][2]), "+f"(acc[mt][nt1][3])
                        : "r"(a[mt][0]), "r"(a[mt][1]), "r"(a[mt][2]), "r"(a[mt][3]),
                          "r"(v.z), "r"(v.w));
                }
            }
        }

        if (slab == 15) {
            #pragma unroll
            for (int mt = 0; mt < 2; ++mt)
                #pragma unroll
                for (int nt = 0; nt < 8; ++nt) {
                    const int jg = pass * H_TILE + warp_n * 64 + nt * 8 + c * 2;
                    const float b1a = smB1[jg], b1b = smB1[jg + 1];
                    const float w2a = smW2[jg], w2b = smW2[jg + 1];
                    const float h0 = fmaxf(acc[mt][nt][0] + b1a, 0.f);
                    const float h1 = fmaxf(acc[mt][nt][1] + b1b, 0.f);
                    const float h2 = fmaxf(acc[mt][nt][2] + b1a, 0.f);
                    const float h3 = fmaxf(acc[mt][nt][3] + b1b, 0.f);
                    psum[mt * 2 + 0] += h0 * w2a + h1 * w2b;
                    psum[mt * 2 + 1] += h2 * w2a + h3 * w2b;
                }
        }
    }

    // ---- reduce across quad (k-cols of frag), then across 2 n-warps ----
    #pragma unroll
    for (int i = 0; i < 4; ++i) {
        psum[i] += __shfl_xor_sync(0xffffffffu, psum[i], 1);
        psum[i] += __shfl_xor_sync(0xffffffffu, psum[i], 2);
    }
    if (c == 0) {
        #pragma unroll
        for (int mt = 0; mt < 2; ++mt) {
            atomicAdd(&smP[warp_m * 32 + mt * 16 + r],     psum[mt * 2 + 0]);
            atomicAdd(&smP[warp_m * 32 + mt * 16 + r + 8], psum[mt * 2 + 1]);
        }
    }
    __syncthreads();

    if (tid < P_TILE) {
        const float logit = smP[tid] + B2[0];
        const int n = n0 + (tid >> 3);
        const int m = m0 + (tid & 7);
        out[(size_t)n * M_GLOB + m] = 1.f / (1.f + expf(-logit));
    }
}

extern "C" void kernel_launch(void* const* d_in, const int* in_sizes, int n_in,
                              void* d_out, int out_size)
{
    const float* E  = (const float*)d_in[0];
    const float* S  = (const float*)d_in[1];
    const float* W1 = (const float*)d_in[2];
    const float* B1 = (const float*)d_in[3];
    const float* W2 = (const float*)d_in[4];
    const float* B2 = (const float*)d_in[5];
    float* out = (float*)d_out;

    convert_w1f_kernel<<<128, 256>>>(W1);

    cudaFuncSetAttribute(support_sp_kernel,
                         cudaFuncAttributeMaxDynamicSharedMemorySize, SMEM_BYTES);
    dim3 grid(M_GLOB / S_SUB, N_GLOB / E_SUB);   // (128, 8) = 1024 CTAs
    support_sp_kernel<<<grid, THREADS, SMEM_BYTES>>>(E, S, B1, W2, B2, out);
}